// round 13
// baseline (speedup 1.0000x reference)
#include <cuda_runtime.h>
#include <cuda_fp16.h>
#include <cstdint>
#include <math.h>

#define Hd     1024
#define Bd     64
#define NDIM   5120
#define FOREST 255
#define KTOT   2048
#define PITCH  144                       // 64 fp16 = 128B + 16B pad (conflict-free)
#define NTILE  160                       // 5 gates x 32 h-columns
#define STAGE_A (128 * PITCH)            // 18432
#define STAGE_BYTES ((128 + NTILE) * PITCH)  // 41472
#define NSTAGE 5
#define SMEM_BARS 1024
#define SMEMT  (SMEM_BARS + NSTAGE * STAGE_BYTES)   // 208384 bytes

// ---------------- static device scratch ----------------
__device__ __half g_Ah[(size_t)16384 * 2048];   // A fp16, row-major [row][k]
__device__ __half g_Wh[(size_t)5120 * 2048];    // W^T fp16, gate-interleaved rows [n'][k]
__device__ float g_bcat[NDIM];                  // bias, ORIGINAL order [gate*1024 + h]
__device__ float g_cbuf[2][(size_t)8192 * Hd];

// ---------------- helpers ----------------
__device__ __forceinline__ uint32_t smem_u32(const void* p) {
    uint32_t a;
    asm("{ .reg .u64 t; cvta.to.shared.u64 t, %1; cvt.u32.u64 %0, t; }" : "=r"(a) : "l"(p));
    return a;
}
__device__ __forceinline__ void cpasync16(uint32_t dst, const void* src) {
    asm volatile("cp.async.cg.shared.global [%0], [%1], 16;" :: "r"(dst), "l"(src));
}
__device__ __forceinline__ void mbar_init(uint32_t a, uint32_t c) {
    asm volatile("mbarrier.init.shared.b64 [%0], %1;" :: "r"(a), "r"(c) : "memory");
}
__device__ __forceinline__ void mbar_arrive(uint32_t a) {
    asm volatile("mbarrier.arrive.shared.b64 _, [%0];" :: "r"(a) : "memory");
}
__device__ __forceinline__ void cpasync_mbar_arrive(uint32_t a) {
    asm volatile("cp.async.mbarrier.arrive.noinc.shared.b64 [%0];" :: "r"(a) : "memory");
}
__device__ __forceinline__ void mbar_wait(uint32_t mbar, int phase) {
    asm volatile(
        "{\n\t.reg .pred P1;\n\t"
        "W_%=:\n\t"
        "mbarrier.try_wait.parity.acquire.cta.shared::cta.b64 P1, [%0], %1, 0x989680;\n\t"
        "@P1 bra.uni D_%=;\n\t"
        "bra.uni W_%=;\n\t"
        "D_%=:\n\t}"
        :: "r"(mbar), "r"(phase) : "memory");
}
__device__ __forceinline__ void ldsm4(uint32_t* r, uint32_t addr) {
    asm volatile("ldmatrix.sync.aligned.m8n8.x4.shared.b16 {%0,%1,%2,%3}, [%4];"
                 : "=r"(r[0]), "=r"(r[1]), "=r"(r[2]), "=r"(r[3]) : "r"(addr));
}
__device__ __forceinline__ void mma16816(float* c, const uint32_t* a, const uint32_t* b) {
    asm volatile("mma.sync.aligned.m16n8k16.row.col.f32.f16.f16.f32 "
                 "{%0,%1,%2,%3}, {%4,%5,%6,%7}, {%8,%9}, {%0,%1,%2,%3};"
                 : "+f"(c[0]), "+f"(c[1]), "+f"(c[2]), "+f"(c[3])
                 : "r"(a[0]), "r"(a[1]), "r"(a[2]), "r"(a[3]), "r"(b[0]), "r"(b[1]));
}
__device__ __forceinline__ uint32_t pk2h(__half a, __half b) {
    __half2 t(a, b);
    return *reinterpret_cast<uint32_t*>(&t);
}
__device__ __forceinline__ uint4 cvt8h(const float* f) {
    uint32_t hw[4];
#pragma unroll
    for (int q = 0; q < 4; q++)
        hw[q] = pk2h(__float2half_rn(f[2*q]), __float2half_rn(f[2*q+1]));
    return make_uint4(hw[0], hw[1], hw[2], hw[3]);
}
__device__ __forceinline__ float sigf(float x)   { return 1.0f / (1.0f + __expf(-x)); }
__device__ __forceinline__ float tanhf_(float x) { return 2.0f / (1.0f + __expf(-2.0f * x)) - 1.0f; }

// ---------------------------------------------------------------------------
// Weight pack with smem transpose: g_Wh[n'][k] = fp16(cat(W;U)[k][n]),
// rows permuted gate-interleaved: n' = (h>>5)*160 + g*32 + (h&31),
// where g = n>>10 (i,o,ck,fl,fr), h = n&1023.
// ---------------------------------------------------------------------------
__global__ __launch_bounds__(256)
void pack_w_kernel(const float* __restrict__ Wi, const float* __restrict__ Ui,
                   const float* __restrict__ Wfl, const float* __restrict__ Ufl,
                   const float* __restrict__ Wfr, const float* __restrict__ Ufr) {
    __shared__ float ts[64][65];
    int k0 = blockIdx.x * 64, n0 = blockIdx.y * 64;
    const float *Wm, *Um; int st, nc0;
    if (n0 < 3072)      { Wm = Wi;  Um = Ui;  st = 3072; nc0 = n0; }
    else if (n0 < 4096) { Wm = Wfl; Um = Ufl; st = 1024; nc0 = n0 - 3072; }
    else                { Wm = Wfr; Um = Ufr; st = 1024; nc0 = n0 - 4096; }
    const float* base = (k0 < 1024) ? Wm : Um;
    int kr0 = k0 & 1023;
    for (int e = threadIdx.x; e < 4096; e += 256) {
        int r = e >> 6, c = e & 63;
        ts[r][c] = base[(size_t)(kr0 + r) * st + nc0 + c];
    }
    __syncthreads();
    for (int u = threadIdx.x; u < 512; u += 256) {
        int nr = u >> 3, ko = u & 7;
        float f[8];
#pragma unroll
        for (int i = 0; i < 8; i++) f[i] = ts[ko * 8 + i][nr];
        int n = n0 + nr;
        int g = n >> 10, h = n & 1023;
        int nprime = (h >> 5) * NTILE + g * 32 + (h & 31);
        size_t off = (size_t)nprime * KTOT + k0 + ko * 8;
        *(uint4*)(g_Wh + off) = cvt8h(f);
    }
}

__global__ void pack_b_kernel(const float* __restrict__ bi,
                              const float* __restrict__ bfl,
                              const float* __restrict__ bfr) {
    int n = blockIdx.x * 256 + threadIdx.x;
    if (n >= NDIM) return;
    g_bcat[n] = (n < 3072) ? bi[n] : (n < 4096) ? bfl[n - 3072] : bfr[n - 4096];
}

// ---------------------------------------------------------------------------
// Embedding: write level-0 A rows (fp16). Row r = b*128 + (l>>1),
// k-half = (l&1)*1024.
// ---------------------------------------------------------------------------
__global__ __launch_bounds__(256)
void embed_kernel(const int* __restrict__ tokens, const float* __restrict__ emb) {
    int idx = blockIdx.x * 256 + threadIdx.x;     // B*256*128 units of 8 elems
    if (idx >= Bd * 256 * 128) return;
    int u = idx & 127, t = idx >> 7;
    int b = t >> 8, l = t & 255;
    int tok = tokens[t];
    const float* s = emb + (size_t)tok * Hd + u * 8;
    float f[8];
    *(float4*)f       = *(const float4*)s;
    *(float4*)(f + 4) = *(const float4*)(s + 4);
    int r = b * 128 + (l >> 1);
    size_t off = (size_t)r * KTOT + (l & 1) * 1024 + u * 8;
    *(uint4*)(g_Ah + off) = cvt8h(f);
}

// ---------------------------------------------------------------------------
// Fused HMMA GEMM + LSTM gates, warp-specialized.
// CTA 128M x 160N (5 gates x 32 h). 8 consumer warps (M-stacked, 16x160 each)
// + 2 producer warps; 5-stage mbarrier ring; no CTA barrier in mainloop.
// acc tile t = gate*4 + q holds gate 'gate' for h-octet q -> all 5 gates of a
// given (row,h) live in one thread. Epilogue does bias+gates and writes
// h (fp32 d_out), h (fp16 next-level A), c (ping-pong) directly; g_pre gone.
// ---------------------------------------------------------------------------
__global__ __launch_bounds__(320, 1)
void gemm_kernel(float* __restrict__ dout, int level) {
    extern __shared__ char smraw[];
    const uint32_t smb = smem_u32(smraw);
    const uint32_t full0 = smb, empty0 = smb + 64;
    const uint32_t stg0 = smb + SMEM_BARS;
    const int tid = threadIdx.x, lane = tid & 31, wid = tid >> 5;
    const int M = Bd * (128 >> level);
    const int mt = blockIdx.x, bn = blockIdx.y;       // bn in [0,32)
    const size_t aRow0 = (size_t)(16384 - (16384 >> level)) + (size_t)mt * 128;
    const size_t bRow0 = (size_t)bn * NTILE;

    if (tid == 0) {
#pragma unroll
        for (int s = 0; s < NSTAGE; s++) {
            mbar_init(full0 + s * 8, 64);
            mbar_init(empty0 + s * 8, 8);
        }
        asm volatile("fence.proxy.async.shared::cta;" ::: "memory");
    }
    __syncthreads();

    if (wid >= 8) {
        // ---- producer: 2 warps, 64 threads ----
        const int ptid = tid - 256;          // 0..63
        const int lc = ptid & 7;             // 16B chunk in row
        const int lr = ptid >> 3;            // 0..7
        int stage = 0, phase = 1;
        for (int it = 0; it < 32; it++) {
            mbar_wait(empty0 + stage * 8, phase);
            uint32_t st = stg0 + stage * STAGE_BYTES;
            int kb = it * 64;
#pragma unroll
            for (int i = 0; i < 16; i++) {           // A: 128 rows
                int row = lr + i * 8;
                cpasync16(st + row * PITCH + lc * 16,
                          g_Ah + (aRow0 + row) * KTOT + kb + lc * 8);
            }
#pragma unroll
            for (int i = 0; i < 20; i++) {           // B: 160 rows
                int row = lr + i * 8;
                cpasync16(st + STAGE_A + row * PITCH + lc * 16,
                          g_Wh + (bRow0 + row) * KTOT + kb + lc * 8);
            }
            cpasync_mbar_arrive(full0 + stage * 8);
            if (++stage == NSTAGE) { stage = 0; phase ^= 1; }
        }
        return;
    }

    // ---- consumers: 8 warps stacked in M, warp tile 16 x 160 ----
    const int wm = wid;

    float acc[20][4];
#pragma unroll
    for (int t = 0; t < 20; t++)
#pragma unroll
        for (int c = 0; c < 4; c++) acc[t][c] = 0.0f;

    const uint32_t aB = stg0 + (wm * 16 + (lane & 15)) * PITCH + (lane >> 4) * 16;
    const uint32_t bB = stg0 + STAGE_A
                      + ((lane & 7) + ((lane >> 4) << 3)) * PITCH
                      + ((lane >> 3) & 1) * 16;

    int stage = 0, phase = 0;
    for (int it = 0; it < 32; it++) {
        mbar_wait(full0 + stage * 8, phase);
        uint32_t sOff = (uint32_t)stage * STAGE_BYTES;
#pragma unroll
        for (int sub = 0; sub < 4; sub++) {
            uint32_t aS = aB + sOff + sub * 32;
            uint32_t bS = bB + sOff + sub * 32;
            uint32_t av[4], bf[10][4];
            ldsm4(av, aS);
#pragma unroll
            for (int nbp = 0; nbp < 10; nbp++)
                ldsm4(bf[nbp], bS + nbp * 16 * PITCH);
#pragma unroll
            for (int nbp = 0; nbp < 10; nbp++) {
                mma16816(acc[2*nbp],   av, bf[nbp]);
                mma16816(acc[2*nbp+1], av, bf[nbp] + 2);
            }
        }
        if (lane == 0) mbar_arrive(empty0 + stage * 8);
        if (++stage == NSTAGE) { stage = 0; phase ^= 1; }
    }

    // ---- fused epilogue: bias + gate math + direct outputs ----
    const int P = 128 >> level;
    const int off = 256 - (256 >> level);
    const size_t rowbase2 = 16384 - (16384 >> (level + 1));
    const int hbase = bn * 32 + (lane & 3) * 2;

#pragma unroll
    for (int half = 0; half < 2; half++) {
        int r = mt * 128 + wm * 16 + (lane >> 2) + half * 8;
        if (r >= M) continue;
        int b = r >> (7 - level);
        int j = r & (P - 1);
        const float* cp = g_cbuf[(level + 1) & 1] + (size_t)r * 2048;
        float* cw = g_cbuf[level & 1] + (size_t)r * 1024;
        float* hw = dout + ((size_t)b * FOREST + off + j) * 1024;
        const int c0 = half * 2;
#pragma unroll
        for (int q = 0; q < 4; q++) {
            int h = hbase + q * 8;
            float2 bi = *(const float2*)(g_bcat + h);
            float2 bo = *(const float2*)(g_bcat + 1024 + h);
            float2 bk = *(const float2*)(g_bcat + 2048 + h);
            float2 bl = *(const float2*)(g_bcat + 3072 + h);
            float2 br = *(const float2*)(g_bcat + 4096 + h);
            float i0  = acc[q][c0]      + bi.x, i1  = acc[q][c0+1]      + bi.y;
            float o0  = acc[4+q][c0]    + bo.x, o1  = acc[4+q][c0+1]    + bo.y;
            float k0v = acc[8+q][c0]    + bk.x, k1v = acc[8+q][c0+1]    + bk.y;
            float l0  = acc[12+q][c0]   + bl.x, l1  = acc[12+q][c0+1]   + bl.y;
            float f0  = acc[16+q][c0]   + br.x, f1  = acc[16+q][c0+1]   + br.y;
            float cl0 = 0.f, cl1 = 0.f, cr0 = 0.f, cr1 = 0.f;
            if (level > 0) {
                float2 clv = *(const float2*)(cp + h);
                float2 crv = *(const float2*)(cp + 1024 + h);
                cl0 = clv.x; cl1 = clv.y; cr0 = crv.x; cr1 = crv.y;
            }
            float c0v = sigf(i0) * tanhf_(k0v) + sigf(l0) * cl0 + sigf(f0) * cr0;
            float c1v = sigf(i1) * tanhf_(k1v) + sigf(l1) * cl1 + sigf(f1) * cr1;
            float h0v = sigf(o0) * tanhf_(c0v);
            float h1v = sigf(o1) * tanhf_(c1v);
            *(float2*)(cw + h) = make_float2(c0v, c1v);
            *(float2*)(hw + h) = make_float2(h0v, h1v);
            if (level < 7) {
                int r2 = b * (P >> 1) + (j >> 1);
                size_t aoff = (rowbase2 + r2) * (size_t)KTOT + (j & 1) * 1024 + h;
                *(uint32_t*)(g_Ah + aoff) = pk2h(__float2half_rn(h0v), __float2half_rn(h1v));
            } else {
                float* hroot = dout + (size_t)Bd * FOREST * 1024 + (size_t)r * 1024;
                float* croot = hroot + (size_t)Bd * 1024;
                *(float2*)(hroot + h) = make_float2(h0v, h1v);
                *(float2*)(croot + h) = make_float2(c0v, c1v);
            }
        }
    }
}

// ---------------------------------------------------------------------------
// launcher (graph-capturable: kernel launches only, default stream)
// ---------------------------------------------------------------------------
extern "C" void kernel_launch(void* const* d_in, const int* in_sizes, int n_in,
                              void* d_out, int out_size) {
    const int*   tokens = (const int*)  d_in[0];
    const float* emb    = (const float*)d_in[1];
    const float* W_iock = (const float*)d_in[2];
    const float* b_iock = (const float*)d_in[3];
    const float* U_iock = (const float*)d_in[4];
    const float* W_fl   = (const float*)d_in[5];
    const float* b_fl   = (const float*)d_in[6];
    const float* U_fl   = (const float*)d_in[7];
    const float* W_fr   = (const float*)d_in[8];
    const float* b_fr   = (const float*)d_in[9];
    const float* U_fr   = (const float*)d_in[10];
    float* out = (float*)d_out;

    static bool attr_set = false;
    if (!attr_set) {
        cudaFuncSetAttribute(gemm_kernel, cudaFuncAttributeMaxDynamicSharedMemorySize, SMEMT);
        attr_set = true;
    }

    pack_w_kernel<<<dim3(32, 80), 256>>>(W_iock, U_iock, W_fl, U_fl, W_fr, U_fr);
    pack_b_kernel<<<20, 256>>>(b_iock, b_fl, b_fr);
    {
        int total = Bd * 256 * 128;
        embed_kernel<<<(total + 255) / 256, 256>>>(tokens, emb);
    }
    for (int level = 0; level < 8; ++level) {
        int M = Bd * (128 >> level);
        dim3 grid((M + 127) / 128, 32);
        gemm_kernel<<<grid, 320, SMEMT>>>(out, level);
    }
}

// round 14
// speedup vs baseline: 1.0476x; 1.0476x over previous
#include <cuda_runtime.h>
#include <cuda_fp16.h>
#include <cstdint>
#include <math.h>

#define Hd     1024
#define Bd     64
#define NDIM   5120
#define FOREST 255
#define KTOT   2048
#define PITCH  144                       // 64 fp16 = 128B + 16B pad (conflict-free)
#define NTILE  160                       // 2 h-groups x (5 gates x 16 h)
#define STAGE_A (128 * PITCH)            // 18432
#define STAGE_BYTES ((128 + NTILE) * PITCH)  // 41472
#define NSTAGE 5
#define SMEM_BARS 1024
#define SMEMT  (SMEM_BARS + NSTAGE * STAGE_BYTES)   // 208384 bytes

// ---------------- static device scratch ----------------
__device__ __half g_Ah[(size_t)16384 * 2048];   // A fp16, row-major [row][k]
__device__ __half g_Wh[(size_t)5120 * 2048];    // W^T fp16, gate-interleaved rows [n'][k]
__device__ float g_bcat[NDIM];                  // bias, ORIGINAL order [gate*1024 + h]
__device__ float g_cbuf[2][(size_t)8192 * Hd];

// ---------------- helpers ----------------
__device__ __forceinline__ uint32_t smem_u32(const void* p) {
    uint32_t a;
    asm("{ .reg .u64 t; cvta.to.shared.u64 t, %1; cvt.u32.u64 %0, t; }" : "=r"(a) : "l"(p));
    return a;
}
__device__ __forceinline__ void cpasync16(uint32_t dst, const void* src) {
    asm volatile("cp.async.cg.shared.global [%0], [%1], 16;" :: "r"(dst), "l"(src));
}
__device__ __forceinline__ void mbar_init(uint32_t a, uint32_t c) {
    asm volatile("mbarrier.init.shared.b64 [%0], %1;" :: "r"(a), "r"(c) : "memory");
}
__device__ __forceinline__ void mbar_arrive(uint32_t a) {
    asm volatile("mbarrier.arrive.shared.b64 _, [%0];" :: "r"(a) : "memory");
}
__device__ __forceinline__ void cpasync_mbar_arrive(uint32_t a) {
    asm volatile("cp.async.mbarrier.arrive.noinc.shared.b64 [%0];" :: "r"(a) : "memory");
}
__device__ __forceinline__ void mbar_wait(uint32_t mbar, int phase) {
    asm volatile(
        "{\n\t.reg .pred P1;\n\t"
        "W_%=:\n\t"
        "mbarrier.try_wait.parity.acquire.cta.shared::cta.b64 P1, [%0], %1, 0x989680;\n\t"
        "@P1 bra.uni D_%=;\n\t"
        "bra.uni W_%=;\n\t"
        "D_%=:\n\t}"
        :: "r"(mbar), "r"(phase) : "memory");
}
__device__ __forceinline__ void ldsm4(uint32_t* r, uint32_t addr) {
    asm volatile("ldmatrix.sync.aligned.m8n8.x4.shared.b16 {%0,%1,%2,%3}, [%4];"
                 : "=r"(r[0]), "=r"(r[1]), "=r"(r[2]), "=r"(r[3]) : "r"(addr));
}
__device__ __forceinline__ void mma16816(float* c, const uint32_t* a, const uint32_t* b) {
    asm volatile("mma.sync.aligned.m16n8k16.row.col.f32.f16.f16.f32 "
                 "{%0,%1,%2,%3}, {%4,%5,%6,%7}, {%8,%9}, {%0,%1,%2,%3};"
                 : "+f"(c[0]), "+f"(c[1]), "+f"(c[2]), "+f"(c[3])
                 : "r"(a[0]), "r"(a[1]), "r"(a[2]), "r"(a[3]), "r"(b[0]), "r"(b[1]));
}
__device__ __forceinline__ uint32_t pk2h(__half a, __half b) {
    __half2 t(a, b);
    return *reinterpret_cast<uint32_t*>(&t);
}
__device__ __forceinline__ uint4 cvt8h(const float* f) {
    uint32_t hw[4];
#pragma unroll
    for (int q = 0; q < 4; q++)
        hw[q] = pk2h(__float2half_rn(f[2*q]), __float2half_rn(f[2*q+1]));
    return make_uint4(hw[0], hw[1], hw[2], hw[3]);
}
__device__ __forceinline__ float sigf(float x)   { return 1.0f / (1.0f + __expf(-x)); }
__device__ __forceinline__ float tanhf_(float x) { return 2.0f / (1.0f + __expf(-2.0f * x)) - 1.0f; }

// ---------------------------------------------------------------------------
// Weight pack with smem transpose: g_Wh[n'][k] = fp16(cat(W;U)[k][n]),
// rows permuted gate-interleaved with h-group 16:
//   n' = (h>>4)*80 + g*16 + (h&15),  g = n>>10 (i,o,ck,fl,fr), h = n&1023.
// ---------------------------------------------------------------------------
__global__ __launch_bounds__(256)
void pack_w_kernel(const float* __restrict__ Wi, const float* __restrict__ Ui,
                   const float* __restrict__ Wfl, const float* __restrict__ Ufl,
                   const float* __restrict__ Wfr, const float* __restrict__ Ufr) {
    __shared__ float ts[64][65];
    int k0 = blockIdx.x * 64, n0 = blockIdx.y * 64;
    const float *Wm, *Um; int st, nc0;
    if (n0 < 3072)      { Wm = Wi;  Um = Ui;  st = 3072; nc0 = n0; }
    else if (n0 < 4096) { Wm = Wfl; Um = Ufl; st = 1024; nc0 = n0 - 3072; }
    else                { Wm = Wfr; Um = Ufr; st = 1024; nc0 = n0 - 4096; }
    const float* base = (k0 < 1024) ? Wm : Um;
    int kr0 = k0 & 1023;
    for (int e = threadIdx.x; e < 4096; e += 256) {
        int r = e >> 6, c = e & 63;
        ts[r][c] = base[(size_t)(kr0 + r) * st + nc0 + c];
    }
    __syncthreads();
    for (int u = threadIdx.x; u < 512; u += 256) {
        int nr = u >> 3, ko = u & 7;
        float f[8];
#pragma unroll
        for (int i = 0; i < 8; i++) f[i] = ts[ko * 8 + i][nr];
        int n = n0 + nr;
        int g = n >> 10, h = n & 1023;
        int nprime = (h >> 4) * 80 + g * 16 + (h & 15);
        size_t off = (size_t)nprime * KTOT + k0 + ko * 8;
        *(uint4*)(g_Wh + off) = cvt8h(f);
    }
}

__global__ void pack_b_kernel(const float* __restrict__ bi,
                              const float* __restrict__ bfl,
                              const float* __restrict__ bfr) {
    int n = blockIdx.x * 256 + threadIdx.x;
    if (n >= NDIM) return;
    g_bcat[n] = (n < 3072) ? bi[n] : (n < 4096) ? bfl[n - 3072] : bfr[n - 4096];
}

// ---------------------------------------------------------------------------
// Embedding: write level-0 A rows (fp16). Row r = b*128 + (l>>1),
// k-half = (l&1)*1024.
// ---------------------------------------------------------------------------
__global__ __launch_bounds__(256)
void embed_kernel(const int* __restrict__ tokens, const float* __restrict__ emb) {
    int idx = blockIdx.x * 256 + threadIdx.x;     // B*256*128 units of 8 elems
    if (idx >= Bd * 256 * 128) return;
    int u = idx & 127, t = idx >> 7;
    int b = t >> 8, l = t & 255;
    int tok = tokens[t];
    const float* s = emb + (size_t)tok * Hd + u * 8;
    float f[8];
    *(float4*)f       = *(const float4*)s;
    *(float4*)(f + 4) = *(const float4*)(s + 4);
    int r = b * 128 + (l >> 1);
    size_t off = (size_t)r * KTOT + (l & 1) * 1024 + u * 8;
    *(uint4*)(g_Ah + off) = cvt8h(f);
}

// ---------------------------------------------------------------------------
// Fused HMMA GEMM + LSTM gates, warp-specialized.
// CTA 128M x 160N. 8 consumer warps in 4M x 2N grid, warp tile 32 x 80
// (= one full 5-gate set for 16 h columns) + 2 producer warps; 5-stage
// mbarrier ring; no CTA-wide barrier in mainloop.
// Warp tile 32x80 keeps the R12 ldsm:MMA ratio (7:20) -> smem not binding.
// acc[mb][2*g+hh] holds gate g, h-octet hh: all 5 gates of a (row,h) in one
// thread. Epilogue: bias + gates in-register; writes h (fp32 d_out),
// h (fp16 next-level A), c (ping-pong). No g_pre.
// ---------------------------------------------------------------------------
__global__ __launch_bounds__(320, 1)
void gemm_kernel(float* __restrict__ dout, int level) {
    extern __shared__ char smraw[];
    const uint32_t smb = smem_u32(smraw);
    const uint32_t full0 = smb, empty0 = smb + 64;
    const uint32_t stg0 = smb + SMEM_BARS;
    const int tid = threadIdx.x, lane = tid & 31, wid = tid >> 5;
    const int M = Bd * (128 >> level);
    const int mt = blockIdx.x, bn = blockIdx.y;       // bn in [0,32)
    const size_t aRow0 = (size_t)(16384 - (16384 >> level)) + (size_t)mt * 128;
    const size_t bRow0 = (size_t)bn * NTILE;

    if (tid == 0) {
#pragma unroll
        for (int s = 0; s < NSTAGE; s++) {
            mbar_init(full0 + s * 8, 64);
            mbar_init(empty0 + s * 8, 8);
        }
        asm volatile("fence.proxy.async.shared::cta;" ::: "memory");
    }
    __syncthreads();

    if (wid >= 8) {
        // ---- producer: 2 warps, 64 threads ----
        const int ptid = tid - 256;          // 0..63
        const int lc = ptid & 7;             // 16B chunk in row
        const int lr = ptid >> 3;            // 0..7
        int stage = 0, phase = 1;
        for (int it = 0; it < 32; it++) {
            mbar_wait(empty0 + stage * 8, phase);
            uint32_t st = stg0 + stage * STAGE_BYTES;
            int kb = it * 64;
#pragma unroll
            for (int i = 0; i < 16; i++) {           // A: 128 rows
                int row = lr + i * 8;
                cpasync16(st + row * PITCH + lc * 16,
                          g_Ah + (aRow0 + row) * KTOT + kb + lc * 8);
            }
#pragma unroll
            for (int i = 0; i < 20; i++) {           // B: 160 rows
                int row = lr + i * 8;
                cpasync16(st + STAGE_A + row * PITCH + lc * 16,
                          g_Wh + (bRow0 + row) * KTOT + kb + lc * 8);
            }
            cpasync_mbar_arrive(full0 + stage * 8);
            if (++stage == NSTAGE) { stage = 0; phase ^= 1; }
        }
        return;
    }

    // ---- consumers: 8 warps, 4M x 2N, warp tile 32 x 80 ----
    const int wm = wid >> 1, wn = wid & 1;

    float acc[2][10][4];
#pragma unroll
    for (int mb = 0; mb < 2; mb++)
#pragma unroll
        for (int t = 0; t < 10; t++)
#pragma unroll
            for (int c = 0; c < 4; c++) acc[mb][t][c] = 0.0f;

    const uint32_t aB = stg0 + (wm * 32 + (lane & 15)) * PITCH + (lane >> 4) * 16;
    const uint32_t bB = stg0 + STAGE_A
                      + (wn * 80 + (lane & 7) + ((lane >> 4) << 3)) * PITCH
                      + ((lane >> 3) & 1) * 16;

    int stage = 0, phase = 0;
    for (int it = 0; it < 32; it++) {
        mbar_wait(full0 + stage * 8, phase);
        uint32_t sOff = (uint32_t)stage * STAGE_BYTES;
#pragma unroll
        for (int sub = 0; sub < 4; sub++) {
            uint32_t aS = aB + sOff + sub * 32;
            uint32_t bS = bB + sOff + sub * 32;
            uint32_t av[2][4], bf[5][4];
            ldsm4(av[0], aS);
            ldsm4(av[1], aS + 16 * PITCH);
#pragma unroll
            for (int nbp = 0; nbp < 5; nbp++)
                ldsm4(bf[nbp], bS + nbp * 16 * PITCH);
#pragma unroll
            for (int nbp = 0; nbp < 5; nbp++)
#pragma unroll
                for (int mb = 0; mb < 2; mb++) {
                    mma16816(acc[mb][2*nbp],   av[mb], bf[nbp]);
                    mma16816(acc[mb][2*nbp+1], av[mb], bf[nbp] + 2);
                }
        }
        if (lane == 0) mbar_arrive(empty0 + stage * 8);
        if (++stage == NSTAGE) { stage = 0; phase ^= 1; }
    }

    // ---- fused epilogue: bias + gate math + direct outputs ----
    const int P = 128 >> level;
    const int off = 256 - (256 >> level);
    const size_t rowbase2 = 16384 - (16384 >> (level + 1));
    const int hwbase = bn * 32 + wn * 16 + (lane & 3) * 2;

#pragma unroll
    for (int mb = 0; mb < 2; mb++) {
#pragma unroll
        for (int half = 0; half < 2; half++) {
            int r = mt * 128 + wm * 32 + mb * 16 + (lane >> 2) + half * 8;
            if (r >= M) continue;
            int b = r >> (7 - level);
            int j = r & (P - 1);
            const float* cp = g_cbuf[(level + 1) & 1] + (size_t)r * 2048;
            float* cw = g_cbuf[level & 1] + (size_t)r * 1024;
            float* hw = dout + ((size_t)b * FOREST + off + j) * 1024;
            const int c0 = half * 2;
#pragma unroll
            for (int hh = 0; hh < 2; hh++) {
                int h = hwbase + hh * 8;
                float2 bi = *(const float2*)(g_bcat + h);
                float2 bo = *(const float2*)(g_bcat + 1024 + h);
                float2 bk = *(const float2*)(g_bcat + 2048 + h);
                float2 bl = *(const float2*)(g_bcat + 3072 + h);
                float2 br = *(const float2*)(g_bcat + 4096 + h);
                float i0  = acc[mb][hh][c0]   + bi.x, i1  = acc[mb][hh][c0+1]   + bi.y;
                float o0  = acc[mb][2+hh][c0] + bo.x, o1  = acc[mb][2+hh][c0+1] + bo.y;
                float k0v = acc[mb][4+hh][c0] + bk.x, k1v = acc[mb][4+hh][c0+1] + bk.y;
                float l0  = acc[mb][6+hh][c0] + bl.x, l1  = acc[mb][6+hh][c0+1] + bl.y;
                float f0  = acc[mb][8+hh][c0] + br.x, f1  = acc[mb][8+hh][c0+1] + br.y;
                float cl0 = 0.f, cl1 = 0.f, cr0 = 0.f, cr1 = 0.f;
                if (level > 0) {
                    float2 clv = *(const float2*)(cp + h);
                    float2 crv = *(const float2*)(cp + 1024 + h);
                    cl0 = clv.x; cl1 = clv.y; cr0 = crv.x; cr1 = crv.y;
                }
                float c0v = sigf(i0) * tanhf_(k0v) + sigf(l0) * cl0 + sigf(f0) * cr0;
                float c1v = sigf(i1) * tanhf_(k1v) + sigf(l1) * cl1 + sigf(f1) * cr1;
                float h0v = sigf(o0) * tanhf_(c0v);
                float h1v = sigf(o1) * tanhf_(c1v);
                *(float2*)(cw + h) = make_float2(c0v, c1v);
                *(float2*)(hw + h) = make_float2(h0v, h1v);
                if (level < 7) {
                    int r2 = b * (P >> 1) + (j >> 1);
                    size_t aoff = (rowbase2 + r2) * (size_t)KTOT + (j & 1) * 1024 + h;
                    *(uint32_t*)(g_Ah + aoff) = pk2h(__float2half_rn(h0v), __float2half_rn(h1v));
                } else {
                    float* hroot = dout + (size_t)Bd * FOREST * 1024 + (size_t)r * 1024;
                    float* croot = hroot + (size_t)Bd * 1024;
                    *(float2*)(hroot + h) = make_float2(h0v, h1v);
                    *(float2*)(croot + h) = make_float2(c0v, c1v);
                }
            }
        }
    }
}

// ---------------------------------------------------------------------------
// launcher (graph-capturable: kernel launches only, default stream)
// ---------------------------------------------------------------------------
extern "C" void kernel_launch(void* const* d_in, const int* in_sizes, int n_in,
                              void* d_out, int out_size) {
    const int*   tokens = (const int*)  d_in[0];
    const float* emb    = (const float*)d_in[1];
    const float* W_iock = (const float*)d_in[2];
    const float* b_iock = (const float*)d_in[3];
    const float* U_iock = (const float*)d_in[4];
    const float* W_fl   = (const float*)d_in[5];
    const float* b_fl   = (const float*)d_in[6];
    const float* U_fl   = (const float*)d_in[7];
    const float* W_fr   = (const float*)d_in[8];
    const float* b_fr   = (const float*)d_in[9];
    const float* U_fr   = (const float*)d_in[10];
    float* out = (float*)d_out;

    static bool attr_set = false;
    if (!attr_set) {
        cudaFuncSetAttribute(gemm_kernel, cudaFuncAttributeMaxDynamicSharedMemorySize, SMEMT);
        attr_set = true;
    }

    pack_w_kernel<<<dim3(32, 80), 256>>>(W_iock, U_iock, W_fl, U_fl, W_fr, U_fr);
    pack_b_kernel<<<20, 256>>>(b_iock, b_fl, b_fr);
    {
        int total = Bd * 256 * 128;
        embed_kernel<<<(total + 255) / 256, 256>>>(tokens, emb);
    }
    for (int level = 0; level < 8; ++level) {
        int M = Bd * (128 >> level);
        dim3 grid((M + 127) / 128, 32);
        gemm_kernel<<<grid, 320, SMEMT>>>(out, level);
    }
}

// round 15
// speedup vs baseline: 1.0913x; 1.0418x over previous
#include <cuda_runtime.h>
#include <cuda_fp16.h>
#include <cstdint>
#include <math.h>

#define Hd     1024
#define Bd     64
#define NDIM   5120
#define FOREST 255
#define KTOT   2048
#define PITCH  144                   // 64 fp16 = 128B + 16B pad (conflict-free)
#define STAGE_A (128 * PITCH)        // 18432
#define STAGE_BYTES (256 * PITCH)    // A 128 rows + B 128 rows = 36864
#define NSTAGE 5
#define SMEM_BARS 1024
#define SMEMT  (SMEM_BARS + NSTAGE * STAGE_BYTES)   // 185344 bytes

// ---------------- static device scratch ----------------
__device__ __half g_Ah[(size_t)16384 * 2048];   // A fp16, row-major [row][k]
__device__ __half g_Wh[(size_t)5120 * 2048];    // W^T fp16, [n][k] (original n order)
__device__ float g_bcat[NDIM];
__device__ __half g_pre[(size_t)8192 * NDIM];   // pre-activations, fp16
__device__ float g_cbuf[2][(size_t)8192 * Hd];

// ---------------- helpers ----------------
__device__ __forceinline__ uint32_t smem_u32(const void* p) {
    uint32_t a;
    asm("{ .reg .u64 t; cvta.to.shared.u64 t, %1; cvt.u32.u64 %0, t; }" : "=r"(a) : "l"(p));
    return a;
}
__device__ __forceinline__ void cpasync16(uint32_t dst, const void* src) {
    asm volatile("cp.async.cg.shared.global [%0], [%1], 16;" :: "r"(dst), "l"(src));
}
__device__ __forceinline__ void mbar_init(uint32_t a, uint32_t c) {
    asm volatile("mbarrier.init.shared.b64 [%0], %1;" :: "r"(a), "r"(c) : "memory");
}
__device__ __forceinline__ void mbar_arrive(uint32_t a) {
    asm volatile("mbarrier.arrive.shared.b64 _, [%0];" :: "r"(a) : "memory");
}
__device__ __forceinline__ void cpasync_mbar_arrive(uint32_t a) {
    asm volatile("cp.async.mbarrier.arrive.noinc.shared.b64 [%0];" :: "r"(a) : "memory");
}
__device__ __forceinline__ void mbar_wait(uint32_t mbar, int phase) {
    asm volatile(
        "{\n\t.reg .pred P1;\n\t"
        "W_%=:\n\t"
        "mbarrier.try_wait.parity.acquire.cta.shared::cta.b64 P1, [%0], %1, 0x989680;\n\t"
        "@P1 bra.uni D_%=;\n\t"
        "bra.uni W_%=;\n\t"
        "D_%=:\n\t}"
        :: "r"(mbar), "r"(phase) : "memory");
}
__device__ __forceinline__ void ldsm4(uint32_t* r, uint32_t addr) {
    asm volatile("ldmatrix.sync.aligned.m8n8.x4.shared.b16 {%0,%1,%2,%3}, [%4];"
                 : "=r"(r[0]), "=r"(r[1]), "=r"(r[2]), "=r"(r[3]) : "r"(addr));
}
__device__ __forceinline__ void mma16816(float* c, const uint32_t* a, const uint32_t* b) {
    asm volatile("mma.sync.aligned.m16n8k16.row.col.f32.f16.f16.f32 "
                 "{%0,%1,%2,%3}, {%4,%5,%6,%7}, {%8,%9}, {%0,%1,%2,%3};"
                 : "+f"(c[0]), "+f"(c[1]), "+f"(c[2]), "+f"(c[3])
                 : "r"(a[0]), "r"(a[1]), "r"(a[2]), "r"(a[3]), "r"(b[0]), "r"(b[1]));
}
__device__ __forceinline__ uint32_t pk2h(__half a, __half b) {
    __half2 t(a, b);
    return *reinterpret_cast<uint32_t*>(&t);
}
__device__ __forceinline__ uint32_t pk2f(float a, float b) {
    return pk2h(__float2half_rn(a), __float2half_rn(b));
}
__device__ __forceinline__ uint4 cvt8h(const float* f) {
    uint32_t hw[4];
#pragma unroll
    for (int q = 0; q < 4; q++)
        hw[q] = pk2f(f[2*q], f[2*q+1]);
    return make_uint4(hw[0], hw[1], hw[2], hw[3]);
}
// 8 fp16 -> 8 fp32
__device__ __forceinline__ void ld8h(const __half* p, float* f) {
    uint4 v = *(const uint4*)p;
    const __half2* h = (const __half2*)&v;
#pragma unroll
    for (int q = 0; q < 4; q++) {
        float2 t = __half22float2(h[q]);
        f[2*q] = t.x; f[2*q+1] = t.y;
    }
}
__device__ __forceinline__ float sigf(float x)   { return 1.0f / (1.0f + __expf(-x)); }
__device__ __forceinline__ float tanhf_(float x) { return 2.0f / (1.0f + __expf(-2.0f * x)) - 1.0f; }

// ---------------------------------------------------------------------------
// Weight pack with smem transpose: g_Wh[n][k] = fp16(cat(W;U)[k][n]).
// ---------------------------------------------------------------------------
__global__ __launch_bounds__(256)
void pack_w_kernel(const float* __restrict__ Wi, const float* __restrict__ Ui,
                   const float* __restrict__ Wfl, const float* __restrict__ Ufl,
                   const float* __restrict__ Wfr, const float* __restrict__ Ufr) {
    __shared__ float ts[64][65];
    int k0 = blockIdx.x * 64, n0 = blockIdx.y * 64;
    const float *Wm, *Um; int st, nc0;
    if (n0 < 3072)      { Wm = Wi;  Um = Ui;  st = 3072; nc0 = n0; }
    else if (n0 < 4096) { Wm = Wfl; Um = Ufl; st = 1024; nc0 = n0 - 3072; }
    else                { Wm = Wfr; Um = Ufr; st = 1024; nc0 = n0 - 4096; }
    const float* base = (k0 < 1024) ? Wm : Um;
    int kr0 = k0 & 1023;
    for (int e = threadIdx.x; e < 4096; e += 256) {
        int r = e >> 6, c = e & 63;
        ts[r][c] = base[(size_t)(kr0 + r) * st + nc0 + c];
    }
    __syncthreads();
    for (int u = threadIdx.x; u < 512; u += 256) {
        int nr = u >> 3, ko = u & 7;
        float f[8];
#pragma unroll
        for (int i = 0; i < 8; i++) f[i] = ts[ko * 8 + i][nr];
        size_t off = (size_t)(n0 + nr) * KTOT + k0 + ko * 8;
        *(uint4*)(g_Wh + off) = cvt8h(f);
    }
}

__global__ void pack_b_kernel(const float* __restrict__ bi,
                              const float* __restrict__ bfl,
                              const float* __restrict__ bfr) {
    int n = blockIdx.x * 256 + threadIdx.x;
    if (n >= NDIM) return;
    g_bcat[n] = (n < 3072) ? bi[n] : (n < 4096) ? bfl[n - 3072] : bfr[n - 4096];
}

// ---------------------------------------------------------------------------
// Embedding: write level-0 A rows (fp16). Row r = b*128 + (l>>1),
// k-half = (l&1)*1024.
// ---------------------------------------------------------------------------
__global__ __launch_bounds__(256)
void embed_kernel(const int* __restrict__ tokens, const float* __restrict__ emb) {
    int idx = blockIdx.x * 256 + threadIdx.x;     // B*256*128 units of 8 elems
    if (idx >= Bd * 256 * 128) return;
    int u = idx & 127, t = idx >> 7;
    int b = t >> 8, l = t & 255;
    int tok = tokens[t];
    const float* s = emb + (size_t)tok * Hd + u * 8;
    float f[8];
    *(float4*)f       = *(const float4*)s;
    *(float4*)(f + 4) = *(const float4*)(s + 4);
    int r = b * 128 + (l >> 1);
    size_t off = (size_t)r * KTOT + (l & 1) * 1024 + u * 8;
    *(uint4*)(g_Ah + off) = cvt8h(f);
}

// ---------------------------------------------------------------------------
// HMMA GEMM, warp-specialized (R12 geometry): pre(M,5120) = A(M,2048) @ W^T.
// CTA 128M x 128N. 8 consumer warps (4x2, 32x64 tiles) + 2 producer warps.
// 5-stage mbarrier ring; no CTA-wide barrier in mainloop.
// Output stored fp16 to g_pre (halves store+reload traffic).
// ---------------------------------------------------------------------------
__global__ __launch_bounds__(320, 1)
void gemm_kernel(int level) {
    extern __shared__ char smraw[];
    const uint32_t smb = smem_u32(smraw);
    const uint32_t full0 = smb, empty0 = smb + 64;
    const uint32_t stg0 = smb + SMEM_BARS;
    const int tid = threadIdx.x, lane = tid & 31, wid = tid >> 5;
    const int M = Bd * (128 >> level);
    const int mt = blockIdx.x, bn = blockIdx.y;
    const size_t aRow0 = (size_t)(16384 - (16384 >> level)) + (size_t)mt * 128;
    const size_t bRow0 = (size_t)bn * 128;

    if (tid == 0) {
#pragma unroll
        for (int s = 0; s < NSTAGE; s++) {
            mbar_init(full0 + s * 8, 64);
            mbar_init(empty0 + s * 8, 8);
        }
        asm volatile("fence.proxy.async.shared::cta;" ::: "memory");
    }
    __syncthreads();

    if (wid >= 8) {
        // ---- producer: 2 warps, 64 threads ----
        const int ptid = tid - 256;          // 0..63
        const int lc = ptid & 7;             // 16B chunk in row
        const int lr = ptid >> 3;            // 0..7
        int stage = 0, phase = 1;
        for (int it = 0; it < 32; it++) {
            mbar_wait(empty0 + stage * 8, phase);
            uint32_t st = stg0 + stage * STAGE_BYTES;
            int kb = it * 64;
#pragma unroll
            for (int i = 0; i < 16; i++) {           // A: 128 rows
                int row = lr + i * 8;
                cpasync16(st + row * PITCH + lc * 16,
                          g_Ah + (aRow0 + row) * KTOT + kb + lc * 8);
            }
#pragma unroll
            for (int i = 0; i < 16; i++) {           // B: 128 rows
                int row = lr + i * 8;
                cpasync16(st + STAGE_A + row * PITCH + lc * 16,
                          g_Wh + (bRow0 + row) * KTOT + kb + lc * 8);
            }
            cpasync_mbar_arrive(full0 + stage * 8);
            if (++stage == NSTAGE) { stage = 0; phase ^= 1; }
        }
        return;
    }

    // ---- consumers: 8 warps, 4M x 2N, warp tile 32 x 64 ----
    const int wm = wid >> 1, wn = wid & 1;

    float acc[2][8][4];
#pragma unroll
    for (int a = 0; a < 2; a++)
#pragma unroll
        for (int b = 0; b < 8; b++)
#pragma unroll
            for (int c = 0; c < 4; c++) acc[a][b][c] = 0.0f;

    const uint32_t aB = stg0 + (wm * 32 + (lane & 15)) * PITCH + (lane >> 4) * 16;
    const uint32_t bB = stg0 + STAGE_A
                      + (wn * 64 + (lane & 7) + ((lane >> 4) << 3)) * PITCH
                      + ((lane >> 3) & 1) * 16;

    int stage = 0, phase = 0;
    for (int it = 0; it < 32; it++) {
        mbar_wait(full0 + stage * 8, phase);
        uint32_t sOff = (uint32_t)stage * STAGE_BYTES;
#pragma unroll
        for (int sub = 0; sub < 4; sub++) {
            uint32_t aS = aB + sOff + sub * 32;
            uint32_t bS = bB + sOff + sub * 32;
            uint32_t av[2][4], bf[4][4];
            ldsm4(av[0], aS);
            ldsm4(av[1], aS + 16 * PITCH);
#pragma unroll
            for (int nbp = 0; nbp < 4; nbp++)
                ldsm4(bf[nbp], bS + nbp * 16 * PITCH);
#pragma unroll
            for (int nbp = 0; nbp < 4; nbp++)
#pragma unroll
                for (int mb = 0; mb < 2; mb++) {
                    mma16816(acc[mb][2*nbp],   av[mb], bf[nbp]);
                    mma16816(acc[mb][2*nbp+1], av[mb], bf[nbp] + 2);
                }
        }
        if (lane == 0) mbar_arrive(empty0 + stage * 8);
        if (++stage == NSTAGE) { stage = 0; phase ^= 1; }
    }

    // epilogue: fp16 stores (guarded for M=64 tail level)
    const int gm0 = mt * 128 + wm * 32;
    const int gn0 = bn * 128 + wn * 64;
#pragma unroll
    for (int mb = 0; mb < 2; mb++) {
        int r0 = gm0 + mb * 16 + (lane >> 2);
#pragma unroll
        for (int nb = 0; nb < 8; nb++) {
            int cc = gn0 + nb * 8 + (lane & 3) * 2;
            if (r0 < M)
                *(uint32_t*)(g_pre + (size_t)r0 * NDIM + cc) =
                    pk2f(acc[mb][nb][0], acc[mb][nb][1]);
            if (r0 + 8 < M)
                *(uint32_t*)(g_pre + (size_t)(r0 + 8) * NDIM + cc) =
                    pk2f(acc[mb][nb][2], acc[mb][nb][3]);
        }
    }
}

// ---------------------------------------------------------------------------
// Gates: bias + LSTM gate math; reads fp16 g_pre; writes h (fp32) to d_out,
// c to ping-pong, and h as next-level A rows (fp16).
// ---------------------------------------------------------------------------
__global__ __launch_bounds__(256)
void gates_kernel(float* __restrict__ dout, int level) {
    const int P = 128 >> level;
    const int M = Bd * P;
    int idx = blockIdx.x * 256 + threadIdx.x;
    if (idx >= M * 128) return;
    int m = idx >> 7, u = idx & 127;
    int col0 = u << 3;

    const __half* prow = g_pre + (size_t)m * NDIM + col0;
    float pi[8], po[8], pk[8], pl[8], pr[8];
    ld8h(prow,        pi);
    ld8h(prow + 1024, po);
    ld8h(prow + 2048, pk);
    ld8h(prow + 3072, pl);
    ld8h(prow + 4096, pr);

    const float* bb = g_bcat + col0;
    float bi[8], bo[8], bk[8], bl[8], br[8];
    *(float4*)bi = *(const float4*)(bb);          *(float4*)(bi+4) = *(const float4*)(bb + 4);
    *(float4*)bo = *(const float4*)(bb + 1024);   *(float4*)(bo+4) = *(const float4*)(bb + 1028);
    *(float4*)bk = *(const float4*)(bb + 2048);   *(float4*)(bk+4) = *(const float4*)(bb + 2052);
    *(float4*)bl = *(const float4*)(bb + 3072);   *(float4*)(bl+4) = *(const float4*)(bb + 3076);
    *(float4*)br = *(const float4*)(bb + 4096);   *(float4*)(br+4) = *(const float4*)(bb + 4100);

    float cl[8] = {0,0,0,0,0,0,0,0}, cr[8] = {0,0,0,0,0,0,0,0};
    if (level > 0) {
        const float* cp = g_cbuf[(level + 1) & 1] + (size_t)m * 2048 + col0;
        *(float4*)cl = *(const float4*)(cp);         *(float4*)(cl+4) = *(const float4*)(cp + 4);
        *(float4*)cr = *(const float4*)(cp + 1024);  *(float4*)(cr+4) = *(const float4*)(cp + 1028);
    }

    float cv[8], hv[8];
#pragma unroll
    for (int i = 0; i < 8; i++) {
        float c = sigf(pi[i] + bi[i]) * tanhf_(pk[i] + bk[i])
                + sigf(pl[i] + bl[i]) * cl[i]
                + sigf(pr[i] + br[i]) * cr[i];
        cv[i] = c;
        hv[i] = sigf(po[i] + bo[i]) * tanhf_(c);
    }

    float* cw = g_cbuf[level & 1] + (size_t)m * Hd + col0;
    *(float4*)cw = *(const float4*)cv;  *(float4*)(cw + 4) = *(const float4*)(cv + 4);

    int b = m >> (7 - level);
    int j = m & (P - 1);
    int off = 256 - (256 >> level);
    float* hw = dout + ((size_t)b * FOREST + off + j) * Hd + col0;
    *(float4*)hw = *(const float4*)hv;  *(float4*)(hw + 4) = *(const float4*)(hv + 4);

    if (level < 7) {
        int r = b * (P >> 1) + (j >> 1);
        size_t rowbase = 16384 - (16384 >> (level + 1));
        size_t aoff = (rowbase + r) * (size_t)KTOT + (j & 1) * 1024 + col0;
        *(uint4*)(g_Ah + aoff) = cvt8h(hv);
    } else {
        float* hroot = dout + (size_t)Bd * FOREST * Hd + (size_t)m * Hd + col0;
        float* croot = hroot + (size_t)Bd * Hd;
        *(float4*)hroot = *(const float4*)hv;  *(float4*)(hroot + 4) = *(const float4*)(hv + 4);
        *(float4*)croot = *(const float4*)cv;  *(float4*)(croot + 4) = *(const float4*)(cv + 4);
    }
}

// ---------------------------------------------------------------------------
// launcher (graph-capturable: kernel launches only, default stream)
// ---------------------------------------------------------------------------
extern "C" void kernel_launch(void* const* d_in, const int* in_sizes, int n_in,
                              void* d_out, int out_size) {
    const int*   tokens = (const int*)  d_in[0];
    const float* emb    = (const float*)d_in[1];
    const float* W_iock = (const float*)d_in[2];
    const float* b_iock = (const float*)d_in[3];
    const float* U_iock = (const float*)d_in[4];
    const float* W_fl   = (const float*)d_in[5];
    const float* b_fl   = (const float*)d_in[6];
    const float* U_fl   = (const float*)d_in[7];
    const float* W_fr   = (const float*)d_in[8];
    const float* b_fr   = (const float*)d_in[9];
    const float* U_fr   = (const float*)d_in[10];
    float* out = (float*)d_out;

    static bool attr_set = false;
    if (!attr_set) {
        cudaFuncSetAttribute(gemm_kernel, cudaFuncAttributeMaxDynamicSharedMemorySize, SMEMT);
        attr_set = true;
    }

    pack_w_kernel<<<dim3(32, 80), 256>>>(W_iock, U_iock, W_fl, U_fl, W_fr, U_fr);
    pack_b_kernel<<<20, 256>>>(b_iock, b_fl, b_fr);
    {
        int total = Bd * 256 * 128;
        embed_kernel<<<(total + 255) / 256, 256>>>(tokens, emb);
    }
    for (int level = 0; level < 8; ++level) {
        int M = Bd * (128 >> level);
        dim3 grid((M + 127) / 128, 40);
        gemm_kernel<<<grid, 320, SMEMT>>>(level);
        int units = M * 128;
        gates_kernel<<<(units + 255) / 256, 256>>>(out, level);
    }
}